// round 16
// baseline (speedup 1.0000x reference)
#include <cuda_runtime.h>
#include <math.h>

#define B 192
#define D 2048
#define H 128
#define LOG2PI 1.8378770664093453f
#define IG 4   // i-rows per main-kernel block

// Scratch (device globals — no allocation allowed)
__device__ __align__(16) float g_h1[B * 2 * H];
__device__ __align__(16) float g_mu[B * D];
__device__ __align__(16) float g_scale[B * D];
__device__ float g_lvpart[B * 8];
// k-major transposed weights (filled by gemm1's z=1 blocks each call)
__device__ __align__(16) float g_w2T[2][H * H];            // [head][k*H + c]
__device__ __align__(16) float g_w3T[2][(size_t)H * D];    // [head][k*D + d]

// ---------------------------------------------------------------------------
// Kernel 1: z=0 blocks: gemm1 with R4's 8x4 warp tiling but 128-THREAD blocks
// (4 warps = 4 colgroups). Same per-warp work/loads as the measured-best
// shape; finer block granularity turns the 384-block/2-blocks-per-SM grid
// from 1.3 waves into ONE wave (R15 ncu: regs=128 -> 296-block wave capacity,
// 88-block straggler tail). z=1 blocks: 32x32 smem-tiled transpose (R15).
// grid = (16 colpairs, 24 rowgroups, 2) x 128 threads = 576 blocks total.
// ---------------------------------------------------------------------------
__global__ void __launch_bounds__(128) gemm1_kernel(
    const float* __restrict__ q,
    const float* __restrict__ mw, const float* __restrict__ mb,
    const float* __restrict__ lw, const float* __restrict__ lb,
    const float* __restrict__ mw2, const float* __restrict__ lw2,
    const float* __restrict__ mw3, const float* __restrict__ lw3)
{
    int tid  = threadIdx.x;

    if (blockIdx.z == 1) {
        // ------- tiled transpose blocks (128 threads) -------
        __shared__ float t[32][33];                  // +1 pad: conflict-free
        int bid  = blockIdx.y * 16 + blockIdx.x;     // 0..383
        int lane = tid & 31;
        int row  = tid >> 5;                         // 0..3

        // tiles 0..511: w3 (both heads, 64 x 4 tiles of 32x32 each)
        // tiles 512..543: w2 (both heads, 4 x 4 tiles each)
        for (int tile = bid; tile < 544; tile += 384) {
            const float* src;
            float* dst;
            int d0, k0, srcW, dstW;
            if (tile < 512) {
                int h  = tile >> 8;                  // 256 tiles per head
                int tl = tile & 255;
                d0 = (tl & 63) * 32;                 // 64 tiles along D
                k0 = (tl >> 6) * 32;                 // 4 tiles along H
                src = h ? lw3 : mw3;  srcW = H;      // [D][H]
                dst = g_w3T[h];       dstW = D;      // [H][D]
            } else {
                int tl = tile - 512;                 // 0..31
                int h  = tl >> 4;
                int t2 = tl & 15;
                d0 = (t2 & 3) * 32;
                k0 = (t2 >> 2) * 32;
                src = h ? lw2 : mw2;  srcW = H;      // [H][H]
                dst = g_w2T[h];       dstW = H;
            }
            __syncthreads();                         // protect previous tile
            #pragma unroll
            for (int i = 0; i < 8; ++i)              // coalesced read (lane->k)
                t[row + i * 4][lane] =
                    src[(size_t)(d0 + row + i * 4) * srcW + k0 + lane];
            __syncthreads();
            #pragma unroll
            for (int i = 0; i < 8; ++i)              // coalesced write (lane->d)
                dst[(size_t)(k0 + row + i * 4) * dstW + d0 + lane] =
                    t[lane][row + i * 4];
        }
        return;
    }

    // ------- gemm1 blocks (8x4 warp tiling, 4 warps/block) -------
    int warp = tid >> 5;                // 0..3
    int lane = tid & 31;
    int cg   = blockIdx.x * 4 + warp;   // colgroup 0..63
    int row0 = blockIdx.y * 8;
    int col0 = cg * 4;

    const float* wbase;
    const float* bbase;
    int clocal;
    if (col0 < H) { wbase = mw; bbase = mb; clocal = col0;     }
    else          { wbase = lw; bbase = lb; clocal = col0 - H; }

    const float4* q4 = (const float4*)q;
    const float4* w4 = (const float4*)wbase;

    float acc[8][4];
    #pragma unroll
    for (int r = 0; r < 8; ++r)
        #pragma unroll
        for (int c = 0; c < 4; ++c) acc[r][c] = 0.f;

    #pragma unroll 4
    for (int it = 0; it < (D / 4) / 32; ++it) {   // 16 iters
        int k4 = lane + it * 32;
        float4 b[4];
        #pragma unroll
        for (int c = 0; c < 4; ++c) b[c] = w4[(size_t)(clocal + c) * (D / 4) + k4];
        #pragma unroll
        for (int r = 0; r < 8; ++r) {
            float4 a = q4[(size_t)(row0 + r) * (D / 4) + k4];
            #pragma unroll
            for (int c = 0; c < 4; ++c)
                acc[r][c] += a.x * b[c].x + a.y * b[c].y
                           + a.z * b[c].z + a.w * b[c].w;
        }
    }

    float bv[4];
    #pragma unroll
    for (int c = 0; c < 4; ++c) bv[c] = bbase[clocal + c];

    #pragma unroll
    for (int r = 0; r < 8; ++r)
        #pragma unroll
        for (int c = 0; c < 4; ++c) {
            float v = acc[r][c];
            #pragma unroll
            for (int o = 16; o; o >>= 1) v += __shfl_xor_sync(0xffffffffu, v, o);
            if (lane == 0)
                g_h1[(row0 + r) * 256 + col0 + c] = fmaxf(v + bv[c], 0.f);
        }
}

// ---------------------------------------------------------------------------
// Kernel 2 (fused layers 2+3, R14-exact): block = (head, 256-col d-tile,
// 8 rows), grid (16, 24) x 256, coalesced k-major weights in both steps.
// ---------------------------------------------------------------------------
__global__ void __launch_bounds__(256) gemm23_kernel(
    const float* __restrict__ mb2, const float* __restrict__ lb2,
    const float* __restrict__ mb3, const float* __restrict__ lb3)
{
    __shared__ float sh1[8][H];
    __shared__ float sh2[8][H];
    __shared__ float red[8][8];

    int tid  = threadIdx.x;
    int row0 = blockIdx.y * 8;
    int head = blockIdx.x >> 3;        // 0 = mu, 1 = lv

    // step 1: load h1 half-rows (8 x 128) coalesced
    #pragma unroll
    for (int i = 0; i < 4; ++i) {
        int idx = tid + i * 256;       // 0..1023
        int r = idx >> 7, k = idx & 127;
        sh1[r][k] = g_h1[(row0 + r) * 256 + head * H + k];
    }
    __syncthreads();

    // step 2: h2 = relu(h1 @ w2T + b2). thread -> (col c, 4 rows)
    {
        const float* wT = g_w2T[head];             // [k*H + c]
        const float* b2 = head ? lb2 : mb2;
        int c    = tid & 127;
        int rgrp = tid >> 7;           // 0 or 1 -> rows rgrp*4..+3
        float a0, a1, a2, a3;
        a0 = a1 = a2 = a3 = b2[c];
        #pragma unroll 4
        for (int k = 0; k < H; ++k) {
            float wv = wT[k * H + c];              // coalesced
            a0 += sh1[rgrp * 4 + 0][k] * wv;
            a1 += sh1[rgrp * 4 + 1][k] * wv;
            a2 += sh1[rgrp * 4 + 2][k] * wv;
            a3 += sh1[rgrp * 4 + 3][k] * wv;
        }
        sh2[rgrp * 4 + 0][c] = fmaxf(a0, 0.f);
        sh2[rgrp * 4 + 1][c] = fmaxf(a1, 0.f);
        sh2[rgrp * 4 + 2][c] = fmaxf(a2, 0.f);
        sh2[rgrp * 4 + 3][c] = fmaxf(a3, 0.f);
    }
    __syncthreads();

    // step 3: layer 3 over this block's 256 d-columns, coalesced w3T
    int d = (blockIdx.x & 7) * 256 + tid;          // 0..2047 within head
    const float* wT3 = g_w3T[head];                // [k*D + d]
    const float* bptr = head ? lb3 : mb3;

    float acc[8];
    #pragma unroll
    for (int r = 0; r < 8; ++r) acc[r] = 0.f;

    #pragma unroll 4
    for (int k = 0; k < H; ++k) {
        float wv = wT3[(size_t)k * D + d];         // coalesced
        #pragma unroll
        for (int r = 0; r < 8; ++r) acc[r] += sh2[r][k] * wv;
    }
    float bias = bptr[d];

    if (!head) {
        #pragma unroll
        for (int r = 0; r < 8; ++r)
            g_mu[(size_t)(row0 + r) * D + d] = fmaxf(acc[r] + bias, 0.f);
    } else {
        int lane = tid & 31, wid = tid >> 5;
        #pragma unroll
        for (int r = 0; r < 8; ++r) {
            float v = fmaxf(acc[r] + bias, 0.f);
            g_scale[(size_t)(row0 + r) * D + d] = expf(0.25f * v);
            #pragma unroll
            for (int o = 16; o; o >>= 1) v += __shfl_xor_sync(0xffffffffu, v, o);
            if (lane == 0) red[wid][r] = v;
        }
        __syncthreads();
        if (tid == 0) {
            #pragma unroll
            for (int r = 0; r < 8; ++r) {
                float sum = 0.f;
                #pragma unroll
                for (int k = 0; k < 8; ++k) sum += red[k][r];
                g_lvpart[(row0 + r) * 8 + (blockIdx.x & 7)] = sum;
            }
        }
    }
}

// ---------------------------------------------------------------------------
// Kernel 3 (HBM-bound mainloop, R10-EXACT — measured best, ~85us/82% DRAM):
// block per (j, 4 i-rows), 256 threads, mu/scale in registers, rows in PAIRS
// (MLP=4; MLP=2 and MLP=8 both measured slower).
// ---------------------------------------------------------------------------
__global__ void __launch_bounds__(256) main_kernel(
    const float* __restrict__ eps,
    float* __restrict__ p,
    float* __restrict__ lp)
{
    __shared__ float red[8][IG];
    __shared__ float s_t;

    int j   = blockIdx.x % B;
    int ig  = blockIdx.x / B;
    int tid = threadIdx.x;

    const float4* m4 = (const float4*)g_mu    + (size_t)j * (D / 4);
    const float4* s4 = (const float4*)g_scale + (size_t)j * (D / 4);
    float4 m0 = m4[tid], m1 = m4[tid + 256];
    float4 s0 = s4[tid], s1 = s4[tid + 256];

    if (tid == 0) {
        float sum = 0.f;
        #pragma unroll
        for (int k = 0; k < 8; ++k) sum += g_lvpart[j * 8 + k];
        s_t = -0.25f * sum - 0.5f * (float)D * LOG2PI;
    }

    float acc[IG];
    #pragma unroll
    for (int rp = 0; rp < IG / 2; ++rp) {        // row pairs
        int ra = rp * 2, rb = rp * 2 + 1;
        size_t rowa = (size_t)(ig * IG + ra) * B + j;
        size_t rowb = (size_t)(ig * IG + rb) * B + j;
        const float4* ea4 = (const float4*)eps + rowa * (D / 4);
        const float4* eb4 = (const float4*)eps + rowb * (D / 4);
        float4*       pa4 = (float4*)p        + rowa * (D / 4);
        float4*       pb4 = (float4*)p        + rowb * (D / 4);

        float4 ea0 = __ldcs(&ea4[tid]);
        float4 ea1 = __ldcs(&ea4[tid + 256]);
        float4 eb0 = __ldcs(&eb4[tid]);
        float4 eb1 = __ldcs(&eb4[tid + 256]);

        float4 o;
        o.x = fmaf(ea0.x, s0.x, m0.x);
        o.y = fmaf(ea0.y, s0.y, m0.y);
        o.z = fmaf(ea0.z, s0.z, m0.z);
        o.w = fmaf(ea0.w, s0.w, m0.w);
        __stcs(&pa4[tid], o);
        o.x = fmaf(ea1.x, s1.x, m1.x);
        o.y = fmaf(ea1.y, s1.y, m1.y);
        o.z = fmaf(ea1.z, s1.z, m1.z);
        o.w = fmaf(ea1.w, s1.w, m1.w);
        __stcs(&pa4[tid + 256], o);
        o.x = fmaf(eb0.x, s0.x, m0.x);
        o.y = fmaf(eb0.y, s0.y, m0.y);
        o.z = fmaf(eb0.z, s0.z, m0.z);
        o.w = fmaf(eb0.w, s0.w, m0.w);
        __stcs(&pb4[tid], o);
        o.x = fmaf(eb1.x, s1.x, m1.x);
        o.y = fmaf(eb1.y, s1.y, m1.y);
        o.z = fmaf(eb1.z, s1.z, m1.z);
        o.w = fmaf(eb1.w, s1.w, m1.w);
        __stcs(&pb4[tid + 256], o);

        acc[ra] = ea0.x * ea0.x + ea0.y * ea0.y + ea0.z * ea0.z + ea0.w * ea0.w
                + ea1.x * ea1.x + ea1.y * ea1.y + ea1.z * ea1.z + ea1.w * ea1.w;
        acc[rb] = eb0.x * eb0.x + eb0.y * eb0.y + eb0.z * eb0.z + eb0.w * eb0.w
                + eb1.x * eb1.x + eb1.y * eb1.y + eb1.z * eb1.z + eb1.w * eb1.w;
    }

    int lane = tid & 31, wid = tid >> 5;
    #pragma unroll
    for (int r = 0; r < IG; ++r) {
        float v = acc[r];
        #pragma unroll
        for (int o = 16; o; o >>= 1) v += __shfl_xor_sync(0xffffffffu, v, o);
        if (lane == 0) red[wid][r] = v;
    }
    __syncthreads();
    if (tid < IG) {
        float v = 0.f;
        #pragma unroll
        for (int k = 0; k < 8; ++k) v += red[k][tid];
        lp[(size_t)(ig * IG + tid) * B + j] = -0.5f * v + s_t;
    }
}

// ---------------------------------------------------------------------------
extern "C" void kernel_launch(void* const* d_in, const int* in_sizes, int n_in,
                              void* d_out, int out_size)
{
    const float* q     = (const float*)d_in[0];
    const float* eps   = (const float*)d_in[1];
    const float* mu_w1 = (const float*)d_in[2];
    const float* mu_b1 = (const float*)d_in[3];
    const float* mu_w2 = (const float*)d_in[4];
    const float* mu_b2 = (const float*)d_in[5];
    const float* mu_w3 = (const float*)d_in[6];
    const float* mu_b3 = (const float*)d_in[7];
    const float* lv_w1 = (const float*)d_in[8];
    const float* lv_b1 = (const float*)d_in[9];
    const float* lv_w2 = (const float*)d_in[10];
    const float* lv_b2 = (const float*)d_in[11];
    const float* lv_w3 = (const float*)d_in[12];
    const float* lv_b3 = (const float*)d_in[13];

    float* p  = (float*)d_out;                       // [B, B, D]
    float* lp = (float*)d_out + (size_t)B * B * D;   // [B, B]

    gemm1_kernel<<<dim3(16, 24, 2), 128>>>(q, mu_w1, mu_b1, lv_w1, lv_b1,
                                           mu_w2, lv_w2, mu_w3, lv_w3);
    gemm23_kernel<<<dim3(16, 24), 256>>>(mu_b2, lv_b2, mu_b3, lv_b3);
    main_kernel<<<B * (B / IG), 256>>>(eps, p, lp);
}

// round 17
// speedup vs baseline: 1.0379x; 1.0379x over previous
#include <cuda_runtime.h>
#include <math.h>

#define B 192
#define D 2048
#define H 128
#define LOG2PI 1.8378770664093453f
#define IG 4   // i-rows per main-kernel block

// Scratch (device globals — no allocation allowed)
__device__ __align__(16) float g_h1[B * 2 * H];
__device__ __align__(16) float g_mu[B * D];
__device__ __align__(16) float g_scale[B * D];
__device__ float g_lvpart[B * 8];
// k-major transposed weights (filled by gemm1's z=1 blocks each call)
__device__ __align__(16) float g_w2T[2][H * H];            // [head][k*H + c]
__device__ __align__(16) float g_w3T[2][(size_t)H * D];    // [head][k*D + d]

// ---------------------------------------------------------------------------
// Kernel 1 (R15-EXACT — R16 proved the 256-thread/8-warp shape's reg=128
// codegen is load-bearing): z=0: gemm1, 8x4 register-tiled warps, 192 blocks.
// z=1: 32x32 smem-tiled transpose of w2/w3 into k-major (read+write coalesced).
// grid = (8, 24, 2) x 256 threads.
// ---------------------------------------------------------------------------
__global__ void __launch_bounds__(256) gemm1_kernel(
    const float* __restrict__ q,
    const float* __restrict__ mw, const float* __restrict__ mb,
    const float* __restrict__ lw, const float* __restrict__ lb,
    const float* __restrict__ mw2, const float* __restrict__ lw2,
    const float* __restrict__ mw3, const float* __restrict__ lw3)
{
    int tid  = threadIdx.x;

    if (blockIdx.z == 1) {
        // ------- tiled transpose blocks -------
        __shared__ float t[32][33];                  // +1 pad: conflict-free
        int bid  = blockIdx.y * 8 + blockIdx.x;      // 0..191
        int lane = tid & 31;
        int row  = tid >> 5;                         // 0..7

        // tiles 0..511: w3 (both heads, 64 x 4 tiles of 32x32 each)
        // tiles 512..543: w2 (both heads, 4 x 4 tiles each)
        for (int tile = bid; tile < 544; tile += 192) {
            const float* src;
            float* dst;
            int d0, k0, srcW, dstW;
            if (tile < 512) {
                int h  = tile >> 8;                  // 256 tiles per head
                int tl = tile & 255;
                d0 = (tl & 63) * 32;                 // 64 tiles along D
                k0 = (tl >> 6) * 32;                 // 4 tiles along H
                src = h ? lw3 : mw3;  srcW = H;      // [D][H]
                dst = g_w3T[h];       dstW = D;      // [H][D]
            } else {
                int tl = tile - 512;                 // 0..31
                int h  = tl >> 4;
                int t2 = tl & 15;
                d0 = (t2 & 3) * 32;
                k0 = (t2 >> 2) * 32;
                src = h ? lw2 : mw2;  srcW = H;      // [H][H]
                dst = g_w2T[h];       dstW = H;
            }
            __syncthreads();                         // protect previous tile
            #pragma unroll
            for (int i = 0; i < 4; ++i)              // coalesced read (lane->k)
                t[row + i * 8][lane] =
                    src[(size_t)(d0 + row + i * 8) * srcW + k0 + lane];
            __syncthreads();
            #pragma unroll
            for (int i = 0; i < 4; ++i)              // coalesced write (lane->d)
                dst[(size_t)(k0 + row + i * 8) * dstW + d0 + lane] =
                    t[lane][row + i * 8];
        }
        return;
    }

    // ------- gemm1 blocks (R4-exact) -------
    int warp = tid >> 5;
    int lane = tid & 31;
    int cg   = blockIdx.x * 8 + warp;   // colgroup 0..63
    int row0 = blockIdx.y * 8;
    int col0 = cg * 4;

    const float* wbase;
    const float* bbase;
    int clocal;
    if (col0 < H) { wbase = mw; bbase = mb; clocal = col0;     }
    else          { wbase = lw; bbase = lb; clocal = col0 - H; }

    const float4* q4 = (const float4*)q;
    const float4* w4 = (const float4*)wbase;

    float acc[8][4];
    #pragma unroll
    for (int r = 0; r < 8; ++r)
        #pragma unroll
        for (int c = 0; c < 4; ++c) acc[r][c] = 0.f;

    #pragma unroll 4
    for (int it = 0; it < (D / 4) / 32; ++it) {   // 16 iters
        int k4 = lane + it * 32;
        float4 b[4];
        #pragma unroll
        for (int c = 0; c < 4; ++c) b[c] = w4[(size_t)(clocal + c) * (D / 4) + k4];
        #pragma unroll
        for (int r = 0; r < 8; ++r) {
            float4 a = q4[(size_t)(row0 + r) * (D / 4) + k4];
            #pragma unroll
            for (int c = 0; c < 4; ++c)
                acc[r][c] += a.x * b[c].x + a.y * b[c].y
                           + a.z * b[c].z + a.w * b[c].w;
        }
    }

    float bv[4];
    #pragma unroll
    for (int c = 0; c < 4; ++c) bv[c] = bbase[clocal + c];

    #pragma unroll
    for (int r = 0; r < 8; ++r)
        #pragma unroll
        for (int c = 0; c < 4; ++c) {
            float v = acc[r][c];
            #pragma unroll
            for (int o = 16; o; o >>= 1) v += __shfl_xor_sync(0xffffffffu, v, o);
            if (lane == 0)
                g_h1[(row0 + r) * 256 + col0 + c] = fmaxf(v + bv[c], 0.f);
        }
}

// ---------------------------------------------------------------------------
// Kernel 2 (fused layers 2+3, R14-exact): block = (head, 256-col d-tile,
// 8 rows), grid (16, 24) x 256, coalesced k-major weights in both steps.
// ---------------------------------------------------------------------------
__global__ void __launch_bounds__(256) gemm23_kernel(
    const float* __restrict__ mb2, const float* __restrict__ lb2,
    const float* __restrict__ mb3, const float* __restrict__ lb3)
{
    __shared__ float sh1[8][H];
    __shared__ float sh2[8][H];
    __shared__ float red[8][8];

    int tid  = threadIdx.x;
    int row0 = blockIdx.y * 8;
    int head = blockIdx.x >> 3;        // 0 = mu, 1 = lv

    // step 1: load h1 half-rows (8 x 128) coalesced
    #pragma unroll
    for (int i = 0; i < 4; ++i) {
        int idx = tid + i * 256;       // 0..1023
        int r = idx >> 7, k = idx & 127;
        sh1[r][k] = g_h1[(row0 + r) * 256 + head * H + k];
    }
    __syncthreads();

    // step 2: h2 = relu(h1 @ w2T + b2). thread -> (col c, 4 rows)
    {
        const float* wT = g_w2T[head];             // [k*H + c]
        const float* b2 = head ? lb2 : mb2;
        int c    = tid & 127;
        int rgrp = tid >> 7;           // 0 or 1 -> rows rgrp*4..+3
        float a0, a1, a2, a3;
        a0 = a1 = a2 = a3 = b2[c];
        #pragma unroll 4
        for (int k = 0; k < H; ++k) {
            float wv = wT[k * H + c];              // coalesced
            a0 += sh1[rgrp * 4 + 0][k] * wv;
            a1 += sh1[rgrp * 4 + 1][k] * wv;
            a2 += sh1[rgrp * 4 + 2][k] * wv;
            a3 += sh1[rgrp * 4 + 3][k] * wv;
        }
        sh2[rgrp * 4 + 0][c] = fmaxf(a0, 0.f);
        sh2[rgrp * 4 + 1][c] = fmaxf(a1, 0.f);
        sh2[rgrp * 4 + 2][c] = fmaxf(a2, 0.f);
        sh2[rgrp * 4 + 3][c] = fmaxf(a3, 0.f);
    }
    __syncthreads();

    // step 3: layer 3 over this block's 256 d-columns, coalesced w3T
    int d = (blockIdx.x & 7) * 256 + tid;          // 0..2047 within head
    const float* wT3 = g_w3T[head];                // [k*D + d]
    const float* bptr = head ? lb3 : mb3;

    float acc[8];
    #pragma unroll
    for (int r = 0; r < 8; ++r) acc[r] = 0.f;

    #pragma unroll 4
    for (int k = 0; k < H; ++k) {
        float wv = wT3[(size_t)k * D + d];         // coalesced
        #pragma unroll
        for (int r = 0; r < 8; ++r) acc[r] += sh2[r][k] * wv;
    }
    float bias = bptr[d];

    if (!head) {
        #pragma unroll
        for (int r = 0; r < 8; ++r)
            g_mu[(size_t)(row0 + r) * D + d] = fmaxf(acc[r] + bias, 0.f);
    } else {
        int lane = tid & 31, wid = tid >> 5;
        #pragma unroll
        for (int r = 0; r < 8; ++r) {
            float v = fmaxf(acc[r] + bias, 0.f);
            g_scale[(size_t)(row0 + r) * D + d] = expf(0.25f * v);
            #pragma unroll
            for (int o = 16; o; o >>= 1) v += __shfl_xor_sync(0xffffffffu, v, o);
            if (lane == 0) red[wid][r] = v;
        }
        __syncthreads();
        if (tid == 0) {
            #pragma unroll
            for (int r = 0; r < 8; ++r) {
                float sum = 0.f;
                #pragma unroll
                for (int k = 0; k < 8; ++k) sum += red[k][r];
                g_lvpart[(row0 + r) * 8 + (blockIdx.x & 7)] = sum;
            }
        }
    }
}

// ---------------------------------------------------------------------------
// Kernel 3 (HBM-bound mainloop, R10 shape — measured best): block per
// (j, 4 i-rows), 256 threads, mu/scale in registers, rows in PAIRS (MLP=4).
// MICRO-FIX vs R15: the tid==0 s_t computation (8 serialized L2 loads) moved
// AFTER the streaming loop so warp 0's eps loads issue immediately; s_t is
// still written before the __syncthreads that guards its consumers.
// ---------------------------------------------------------------------------
__global__ void __launch_bounds__(256) main_kernel(
    const float* __restrict__ eps,
    float* __restrict__ p,
    float* __restrict__ lp)
{
    __shared__ float red[8][IG];
    __shared__ float s_t;

    int j   = blockIdx.x % B;
    int ig  = blockIdx.x / B;
    int tid = threadIdx.x;

    const float4* m4 = (const float4*)g_mu    + (size_t)j * (D / 4);
    const float4* s4 = (const float4*)g_scale + (size_t)j * (D / 4);
    float4 m0 = m4[tid], m1 = m4[tid + 256];
    float4 s0 = s4[tid], s1 = s4[tid + 256];

    float acc[IG];
    #pragma unroll
    for (int rp = 0; rp < IG / 2; ++rp) {        // row pairs
        int ra = rp * 2, rb = rp * 2 + 1;
        size_t rowa = (size_t)(ig * IG + ra) * B + j;
        size_t rowb = (size_t)(ig * IG + rb) * B + j;
        const float4* ea4 = (const float4*)eps + rowa * (D / 4);
        const float4* eb4 = (const float4*)eps + rowb * (D / 4);
        float4*       pa4 = (float4*)p        + rowa * (D / 4);
        float4*       pb4 = (float4*)p        + rowb * (D / 4);

        float4 ea0 = __ldcs(&ea4[tid]);
        float4 ea1 = __ldcs(&ea4[tid + 256]);
        float4 eb0 = __ldcs(&eb4[tid]);
        float4 eb1 = __ldcs(&eb4[tid + 256]);

        float4 o;
        o.x = fmaf(ea0.x, s0.x, m0.x);
        o.y = fmaf(ea0.y, s0.y, m0.y);
        o.z = fmaf(ea0.z, s0.z, m0.z);
        o.w = fmaf(ea0.w, s0.w, m0.w);
        __stcs(&pa4[tid], o);
        o.x = fmaf(ea1.x, s1.x, m1.x);
        o.y = fmaf(ea1.y, s1.y, m1.y);
        o.z = fmaf(ea1.z, s1.z, m1.z);
        o.w = fmaf(ea1.w, s1.w, m1.w);
        __stcs(&pa4[tid + 256], o);
        o.x = fmaf(eb0.x, s0.x, m0.x);
        o.y = fmaf(eb0.y, s0.y, m0.y);
        o.z = fmaf(eb0.z, s0.z, m0.z);
        o.w = fmaf(eb0.w, s0.w, m0.w);
        __stcs(&pb4[tid], o);
        o.x = fmaf(eb1.x, s1.x, m1.x);
        o.y = fmaf(eb1.y, s1.y, m1.y);
        o.z = fmaf(eb1.z, s1.z, m1.z);
        o.w = fmaf(eb1.w, s1.w, m1.w);
        __stcs(&pb4[tid + 256], o);

        acc[ra] = ea0.x * ea0.x + ea0.y * ea0.y + ea0.z * ea0.z + ea0.w * ea0.w
                + ea1.x * ea1.x + ea1.y * ea1.y + ea1.z * ea1.z + ea1.w * ea1.w;
        acc[rb] = eb0.x * eb0.x + eb0.y * eb0.y + eb0.z * eb0.z + eb0.w * eb0.w
                + eb1.x * eb1.x + eb1.y * eb1.y + eb1.z * eb1.z + eb1.w * eb1.w;
    }

    // s_t AFTER the stream (consumers are behind the __syncthreads below)
    if (tid == 0) {
        float sum = 0.f;
        #pragma unroll
        for (int k = 0; k < 8; ++k) sum += g_lvpart[j * 8 + k];
        s_t = -0.25f * sum - 0.5f * (float)D * LOG2PI;
    }

    int lane = tid & 31, wid = tid >> 5;
    #pragma unroll
    for (int r = 0; r < IG; ++r) {
        float v = acc[r];
        #pragma unroll
        for (int o = 16; o; o >>= 1) v += __shfl_xor_sync(0xffffffffu, v, o);
        if (lane == 0) red[wid][r] = v;
    }
    __syncthreads();
    if (tid < IG) {
        float v = 0.f;
        #pragma unroll
        for (int k = 0; k < 8; ++k) v += red[k][tid];
        lp[(size_t)(ig * IG + tid) * B + j] = -0.5f * v + s_t;
    }
}

// ---------------------------------------------------------------------------
extern "C" void kernel_launch(void* const* d_in, const int* in_sizes, int n_in,
                              void* d_out, int out_size)
{
    const float* q     = (const float*)d_in[0];
    const float* eps   = (const float*)d_in[1];
    const float* mu_w1 = (const float*)d_in[2];
    const float* mu_b1 = (const float*)d_in[3];
    const float* mu_w2 = (const float*)d_in[4];
    const float* mu_b2 = (const float*)d_in[5];
    const float* mu_w3 = (const float*)d_in[6];
    const float* mu_b3 = (const float*)d_in[7];
    const float* lv_w1 = (const float*)d_in[8];
    const float* lv_b1 = (const float*)d_in[9];
    const float* lv_w2 = (const float*)d_in[10];
    const float* lv_b2 = (const float*)d_in[11];
    const float* lv_w3 = (const float*)d_in[12];
    const float* lv_b3 = (const float*)d_in[13];

    float* p  = (float*)d_out;                       // [B, B, D]
    float* lp = (float*)d_out + (size_t)B * B * D;   // [B, B]

    gemm1_kernel<<<dim3(8, 24, 2), 256>>>(q, mu_w1, mu_b1, lv_w1, lv_b1,
                                          mu_w2, lv_w2, mu_w3, lv_w3);
    gemm23_kernel<<<dim3(16, 24), 256>>>(mu_b2, lv_b2, mu_b3, lv_b3);
    main_kernel<<<B * (B / IG), 256>>>(eps, p, lp);
}